// round 1
// baseline (speedup 1.0000x reference)
#include <cuda_runtime.h>

#define BB 4
#define LL 1024
#define DD 1024
#define HH 16
#define HD 64
#define BH (BB*HH)
#define SCALE 0.125f

// Scratch: q/k/v in [BH][L][HD] fp32 layout (16 MB each)
__device__ float g_q[BH * LL * HD];
__device__ float g_k[BH * LL * HD];
__device__ float g_v[BH * LL * HD];

// ---------------------------------------------------------------------------
// Kernel 1: QKV projection. C[4096,3072] = x[4096,1024] @ W[1024,3072] + b,
// scattered into g_q/g_k/g_v as [BH][L][HD].
// 128x128 tile, BK=16, 8x8 per thread, 256 threads.
// ---------------------------------------------------------------------------
__global__ __launch_bounds__(256) void qkv_kernel(const float* __restrict__ x,
                                                  const float* __restrict__ w,
                                                  const float* __restrict__ bias) {
    __shared__ float As[16][128];   // A transposed: As[k][m]
    __shared__ float Bs[16][128];   // Bs[k][n]
    const int m0 = blockIdx.y * 128;
    const int n0 = blockIdx.x * 128;
    const int t  = threadIdx.x;
    const int tx = t & 15, ty = t >> 4;

    float acc[8][8];
#pragma unroll
    for (int i = 0; i < 8; i++)
#pragma unroll
        for (int j = 0; j < 8; j++) acc[i][j] = 0.f;

    for (int k0 = 0; k0 < 1024; k0 += 16) {
#pragma unroll
        for (int p = 0; p < 2; p++) {
            int f = t + p * 256;
            // A tile: 128 rows x 16 k
            int arow = f >> 2, akg = (f & 3) * 4;
            float4 a4 = *(const float4*)(x + (size_t)(m0 + arow) * 1024 + k0 + akg);
            As[akg + 0][arow] = a4.x;
            As[akg + 1][arow] = a4.y;
            As[akg + 2][arow] = a4.z;
            As[akg + 3][arow] = a4.w;
            // B tile: 16 k x 128 n
            int bk = f >> 5, bng = (f & 31) * 4;
            *(float4*)(&Bs[bk][bng]) =
                *(const float4*)(w + (size_t)(k0 + bk) * 3072 + n0 + bng);
        }
        __syncthreads();
#pragma unroll
        for (int kk = 0; kk < 16; kk++) {
            float a[8], b[8];
            *(float4*)(a)     = *(const float4*)(&As[kk][ty * 8]);
            *(float4*)(a + 4) = *(const float4*)(&As[kk][ty * 8 + 4]);
            *(float4*)(b)     = *(const float4*)(&Bs[kk][tx * 8]);
            *(float4*)(b + 4) = *(const float4*)(&Bs[kk][tx * 8 + 4]);
#pragma unroll
            for (int i = 0; i < 8; i++)
#pragma unroll
                for (int j = 0; j < 8; j++) acc[i][j] += a[i] * b[j];
        }
        __syncthreads();
    }

    // Epilogue: add bias, scatter to q/k/v [BH][L][HD]
#pragma unroll
    for (int i = 0; i < 8; i++) {
        int m = m0 + ty * 8 + i;
        int bb = m >> 10, l = m & 1023;
#pragma unroll
        for (int jg = 0; jg < 2; jg++) {
            int n = n0 + tx * 8 + jg * 4;   // 4 consecutive cols, no 64-boundary cross
            int which = n >> 10;
            int rem = n & 1023;
            int h = rem >> 6, hd = rem & 63;
            float* dst = (which == 0) ? g_q : ((which == 1) ? g_k : g_v);
            float4 v4;
            v4.x = acc[i][jg * 4 + 0] + bias[n + 0];
            v4.y = acc[i][jg * 4 + 1] + bias[n + 1];
            v4.z = acc[i][jg * 4 + 2] + bias[n + 2];
            v4.w = acc[i][jg * 4 + 3] + bias[n + 3];
            *(float4*)(dst + (((size_t)bb * HH + h) * LL + l) * HD + hd) = v4;
        }
    }
}

// ---------------------------------------------------------------------------
// Kernel 2: fused attention with relative position bias + online softmax.
// Block = (l-tile of 64 rows) x (one b,h). Streams 16 r-tiles of 64.
// ---------------------------------------------------------------------------
struct SmemAttn {
    float Qs[64][64];    // transposed: Qs[d][l]
    float Ks[64][64];    // transposed: Ks[d][r]
    float Vs[64][64];    // natural:    Vs[r][d]
    float Es[64][128];   // transposed: Es[d][j]  (band of dist_emb rows)
    float S[64][68];     // S[r][l] (transposed score tile, padded)
    float red[4][64];
    float m_s[64];
    float s_s[64];
    float fac_s[64];
};

__global__ __launch_bounds__(256) void attn_kernel(const float* __restrict__ dist_emb,
                                                   float* __restrict__ out) {
    extern __shared__ char smem_raw[];
    SmemAttn& sm = *(SmemAttn*)smem_raw;

    const int bh = blockIdx.y;
    const int l0 = blockIdx.x * 64;
    const int b  = bh >> 4;
    const int h  = bh & 15;
    const int t  = threadIdx.x;
    const int tx = t & 15, ty = t >> 4;

    const float* qp = g_q + (size_t)bh * LL * HD;
    const float* kp = g_k + (size_t)bh * LL * HD;
    const float* vp = g_v + (size_t)bh * LL * HD;

    // Load Q tile transposed: Qs[d][l]
#pragma unroll
    for (int p = 0; p < 4; p++) {
        int f = t + p * 256;
        int l = f >> 4, dg = (f & 15) * 4;
        float4 q4 = *(const float4*)(qp + (size_t)(l0 + l) * HD + dg);
        sm.Qs[dg + 0][l] = q4.x;
        sm.Qs[dg + 1][l] = q4.y;
        sm.Qs[dg + 2][l] = q4.z;
        sm.Qs[dg + 3][l] = q4.w;
    }
    if (t < 64) { sm.m_s[t] = -1e30f; sm.s_s[t] = 0.f; }

    float o_acc[4][4];
#pragma unroll
    for (int i = 0; i < 4; i++)
#pragma unroll
        for (int j = 0; j < 4; j++) o_acc[i][j] = 0.f;

    __syncthreads();

    const int lc = t & 63;      // softmax: l column handled
    const int g  = t >> 6;      // softmax: r-chunk group (0..3)

    for (int r0 = 0; r0 < LL; r0 += 64) {
        // ---- load K (transposed), V (natural) ----
#pragma unroll
        for (int p = 0; p < 4; p++) {
            int f = t + p * 256;
            int r = f >> 4, dg = (f & 15) * 4;
            float4 k4 = *(const float4*)(kp + (size_t)(r0 + r) * HD + dg);
            sm.Ks[dg + 0][r] = k4.x;
            sm.Ks[dg + 1][r] = k4.y;
            sm.Ks[dg + 2][r] = k4.z;
            sm.Ks[dg + 3][r] = k4.w;
            *(float4*)(&sm.Vs[r][dg]) = *(const float4*)(vp + (size_t)(r0 + r) * HD + dg);
        }
        // ---- load E band transposed: Es[d][j], j in [0,127), jg = jbase + j ----
        const int jbase = l0 - r0 + 960;
#pragma unroll
        for (int p = 0; p < 8; p++) {
            int f = t + p * 256;
            int j = f >> 4, dg = (f & 15) * 4;
            float4 e4 = make_float4(0.f, 0.f, 0.f, 0.f);
            if (j < 127)
                e4 = *(const float4*)(dist_emb + (size_t)(jbase + j) * HD + dg);
            sm.Es[dg + 0][j] = e4.x;
            sm.Es[dg + 1][j] = e4.y;
            sm.Es[dg + 2][j] = e4.z;
            sm.Es[dg + 3][j] = e4.w;
        }
        __syncthreads();

        // ---- S = Q @ K^T (store transposed, pre-scaled) ----
        {
            float s_reg[4][4];
#pragma unroll
            for (int i = 0; i < 4; i++)
#pragma unroll
                for (int j = 0; j < 4; j++) s_reg[i][j] = 0.f;
#pragma unroll 16
            for (int d = 0; d < 64; d++) {
                float4 qa = *(const float4*)(&sm.Qs[d][ty * 4]);
                float4 kb = *(const float4*)(&sm.Ks[d][tx * 4]);
                float a[4] = {qa.x, qa.y, qa.z, qa.w};
                float bq[4] = {kb.x, kb.y, kb.z, kb.w};
#pragma unroll
                for (int i = 0; i < 4; i++)
#pragma unroll
                    for (int j = 0; j < 4; j++) s_reg[i][j] += a[i] * bq[j];
            }
#pragma unroll
            for (int i = 0; i < 4; i++)
#pragma unroll
                for (int j = 0; j < 4; j++)
                    sm.S[tx * 4 + j][ty * 4 + i] = s_reg[i][j] * SCALE;
        }
        __syncthreads();

        // ---- QE = Q @ E_band^T, scatter-add along diagonals ----
        {
            float qe[4][8];
#pragma unroll
            for (int i = 0; i < 4; i++)
#pragma unroll
                for (int j = 0; j < 8; j++) qe[i][j] = 0.f;
#pragma unroll 8
            for (int d = 0; d < 64; d++) {
                float4 qa = *(const float4*)(&sm.Qs[d][ty * 4]);
                float4 e0 = *(const float4*)(&sm.Es[d][tx * 8]);
                float4 e1 = *(const float4*)(&sm.Es[d][tx * 8 + 4]);
                float a[4] = {qa.x, qa.y, qa.z, qa.w};
                float e[8] = {e0.x, e0.y, e0.z, e0.w, e1.x, e1.y, e1.z, e1.w};
#pragma unroll
                for (int i = 0; i < 4; i++)
#pragma unroll
                    for (int j = 0; j < 8; j++) qe[i][j] += a[i] * e[j];
            }
#pragma unroll
            for (int i = 0; i < 4; i++) {
                int l = ty * 4 + i;
#pragma unroll
                for (int jj = 0; jj < 8; jj++) {
                    int r = l - (tx * 8 + jj) + 63;
                    if (r >= 0 && r < 64) sm.S[r][l] += qe[i][jj] * SCALE;
                }
            }
        }
        __syncthreads();

        // ---- KE = K @ E_band^T, scatter-add along diagonals ----
        {
            float ke[4][8];
#pragma unroll
            for (int i = 0; i < 4; i++)
#pragma unroll
                for (int j = 0; j < 8; j++) ke[i][j] = 0.f;
#pragma unroll 8
            for (int d = 0; d < 64; d++) {
                float4 ka = *(const float4*)(&sm.Ks[d][ty * 4]);
                float4 e0 = *(const float4*)(&sm.Es[d][tx * 8]);
                float4 e1 = *(const float4*)(&sm.Es[d][tx * 8 + 4]);
                float a[4] = {ka.x, ka.y, ka.z, ka.w};
                float e[8] = {e0.x, e0.y, e0.z, e0.w, e1.x, e1.y, e1.z, e1.w};
#pragma unroll
                for (int i = 0; i < 4; i++)
#pragma unroll
                    for (int j = 0; j < 8; j++) ke[i][j] += a[i] * e[j];
            }
#pragma unroll
            for (int i = 0; i < 4; i++) {
                int r = ty * 4 + i;
#pragma unroll
                for (int jj = 0; jj < 8; jj++) {
                    int l = r + (tx * 8 + jj) - 63;
                    if (l >= 0 && l < 64) sm.S[r][l] += ke[i][jj] * SCALE;
                }
            }
        }
        __syncthreads();

        // ---- online softmax update ----
        {
            float pm = -1e30f;
#pragma unroll
            for (int rr = g * 16; rr < g * 16 + 16; rr++)
                pm = fmaxf(pm, sm.S[rr][lc]);
            sm.red[g][lc] = pm;
        }
        __syncthreads();
        if (t < 64) {
            float tm = fmaxf(fmaxf(sm.red[0][t], sm.red[1][t]),
                             fmaxf(sm.red[2][t], sm.red[3][t]));
            float mo = sm.m_s[t];
            float mn = fmaxf(mo, tm);
            float fac = __expf(mo - mn);
            sm.m_s[t] = mn;
            sm.fac_s[t] = fac;
            sm.s_s[t] *= fac;
        }
        __syncthreads();
        {
            float mn = sm.m_s[lc];
            float ps = 0.f;
#pragma unroll
            for (int rr = g * 16; rr < g * 16 + 16; rr++) {
                float pv = __expf(sm.S[rr][lc] - mn);
                sm.S[rr][lc] = pv;
                ps += pv;
            }
            sm.red[g][lc] = ps;
        }
        __syncthreads();
        if (t < 64)
            sm.s_s[t] += sm.red[0][t] + sm.red[1][t] + sm.red[2][t] + sm.red[3][t];

        // rescale output accumulators
#pragma unroll
        for (int i = 0; i < 4; i++) {
            float fac = sm.fac_s[ty * 4 + i];
#pragma unroll
            for (int j = 0; j < 4; j++) o_acc[i][j] *= fac;
        }

        // ---- O += P @ V ----
#pragma unroll 16
        for (int rr = 0; rr < 64; rr++) {
            float4 pa = *(const float4*)(&sm.S[rr][ty * 4]);
            float4 vb = *(const float4*)(&sm.Vs[rr][tx * 4]);
            float a[4] = {pa.x, pa.y, pa.z, pa.w};
            float v[4] = {vb.x, vb.y, vb.z, vb.w};
#pragma unroll
            for (int i = 0; i < 4; i++)
#pragma unroll
                for (int j = 0; j < 4; j++) o_acc[i][j] += a[i] * v[j];
        }
        __syncthreads();
    }

    // ---- epilogue: divide by softmax sum, write [B,L,D] ----
#pragma unroll
    for (int i = 0; i < 4; i++) {
        int l = l0 + ty * 4 + i;
        float inv = 1.f / sm.s_s[ty * 4 + i];
        float4 v4;
        v4.x = o_acc[i][0] * inv;
        v4.y = o_acc[i][1] * inv;
        v4.z = o_acc[i][2] * inv;
        v4.w = o_acc[i][3] * inv;
        *(float4*)(out + ((size_t)b * LL + l) * DD + h * HD + tx * 4) = v4;
    }
}

// ---------------------------------------------------------------------------
extern "C" void kernel_launch(void* const* d_in, const int* in_sizes, int n_in,
                              void* d_out, int out_size) {
    const float* x        = (const float*)d_in[0];
    const float* Wqkv     = (const float*)d_in[1];
    const float* bqkv     = (const float*)d_in[2];
    const float* dist_emb = (const float*)d_in[3];
    float* out = (float*)d_out;

    (void)in_sizes; (void)n_in; (void)out_size;

    cudaFuncSetAttribute(attn_kernel, cudaFuncAttributeMaxDynamicSharedMemorySize,
                         (int)sizeof(SmemAttn));

    qkv_kernel<<<dim3(24, 32), 256>>>(x, Wqkv, bqkv);
    attn_kernel<<<dim3(16, 64), 256, sizeof(SmemAttn)>>>(dist_emb, out);
}

// round 3
// speedup vs baseline: 2.8397x; 2.8397x over previous
#include <cuda_runtime.h>
#include <cstdint>

#define BB 4
#define LL 1024
#define DD 1024
#define HH 16
#define HD 64
#define BH (BB*HH)
#define SCALE 0.125f

// q/k/v scratch, stored as tf32 bit patterns in float slots. [BH][L][HD]
__device__ float g_q[BH * LL * HD];
__device__ float g_k[BH * LL * HD];
__device__ float g_v[BH * LL * HD];

__device__ __forceinline__ uint32_t f2tf(float f) {
    uint32_t u;
    asm("cvt.rna.tf32.f32 %0, %1;" : "=r"(u) : "f"(f));
    return u;
}
__device__ __forceinline__ uint32_t fbits(float f) { return __float_as_uint(f); }

__device__ __forceinline__ void mma_tf32(float c[4], uint32_t a0, uint32_t a1,
                                         uint32_t a2, uint32_t a3,
                                         uint32_t b0, uint32_t b1) {
    asm volatile(
        "mma.sync.aligned.m16n8k8.row.col.f32.tf32.tf32.f32 "
        "{%0,%1,%2,%3},{%4,%5,%6,%7},{%8,%9},{%0,%1,%2,%3};"
        : "+f"(c[0]), "+f"(c[1]), "+f"(c[2]), "+f"(c[3])
        : "r"(a0), "r"(a1), "r"(a2), "r"(a3), "r"(b0), "r"(b1));
}

// ---------------------------------------------------------------------------
// Kernel 1: QKV projection with tf32 mma. C[4096,3072] = x @ W + b.
// Block tile 128x128, BK=16, 8 warps each 32x64 (2 m-frags x 8 n-frags).
// ---------------------------------------------------------------------------
#define AS_STRIDE 20
#define BS_STRIDE 136

__global__ __launch_bounds__(256) void qkv_kernel(const float* __restrict__ x,
                                                  const float* __restrict__ w,
                                                  const float* __restrict__ bias) {
    __shared__ float As[128 * AS_STRIDE];   // [m][k] tf32 bits
    __shared__ float Bs[16 * BS_STRIDE];    // [k][n] tf32 bits

    const int t    = threadIdx.x;
    const int lane = t & 31;
    const int wrp  = t >> 5;
    const int gid  = lane >> 2;
    const int t4   = lane & 3;
    const int m0 = blockIdx.y * 128;
    const int n0 = blockIdx.x * 128;
    const int mwb = (wrp & 3) * 32;
    const int nwb = (wrp >> 2) * 64;

    float cacc[2][8][4];
#pragma unroll
    for (int mt = 0; mt < 2; mt++)
#pragma unroll
        for (int nt = 0; nt < 8; nt++)
#pragma unroll
            for (int e = 0; e < 4; e++) cacc[mt][nt][e] = 0.f;

    // per-thread load coords
    int xrow[2], xk[2], wrow[2], wn[2];
#pragma unroll
    for (int p = 0; p < 2; p++) {
        int f = t + p * 256;
        xrow[p] = f >> 2;  xk[p] = (f & 3) * 4;       // 128 rows x 16 k
        wrow[p] = f >> 5;  wn[p] = (f & 31) * 4;      // 16 k x 128 n  (FIXED)
    }

    float4 xa[2], wb[2];
#pragma unroll
    for (int p = 0; p < 2; p++) {
        xa[p] = *(const float4*)(x + (size_t)(m0 + xrow[p]) * 1024 + 0 + xk[p]);
        wb[p] = *(const float4*)(w + (size_t)(0 + wrow[p]) * 3072 + n0 + wn[p]);
    }

    for (int k0 = 0; k0 < 1024; k0 += 16) {
        __syncthreads();
#pragma unroll
        for (int p = 0; p < 2; p++) {
            float* a = &As[xrow[p] * AS_STRIDE + xk[p]];
            a[0] = __uint_as_float(f2tf(xa[p].x));
            a[1] = __uint_as_float(f2tf(xa[p].y));
            a[2] = __uint_as_float(f2tf(xa[p].z));
            a[3] = __uint_as_float(f2tf(xa[p].w));
            float* bq = &Bs[wrow[p] * BS_STRIDE + wn[p]];
            bq[0] = __uint_as_float(f2tf(wb[p].x));
            bq[1] = __uint_as_float(f2tf(wb[p].y));
            bq[2] = __uint_as_float(f2tf(wb[p].z));
            bq[3] = __uint_as_float(f2tf(wb[p].w));
        }
        __syncthreads();
        if (k0 + 16 < 1024) {
#pragma unroll
            for (int p = 0; p < 2; p++) {
                xa[p] = *(const float4*)(x + (size_t)(m0 + xrow[p]) * 1024 + (k0 + 16) + xk[p]);
                wb[p] = *(const float4*)(w + (size_t)((k0 + 16) + wrow[p]) * 3072 + n0 + wn[p]);
            }
        }
#pragma unroll
        for (int ks = 0; ks < 2; ks++) {
            const int kb = ks * 8;
            uint32_t a[2][4];
#pragma unroll
            for (int mt = 0; mt < 2; mt++) {
                int base = mwb + mt * 16;
                a[mt][0] = fbits(As[(base + gid) * AS_STRIDE + kb + t4]);
                a[mt][1] = fbits(As[(base + gid + 8) * AS_STRIDE + kb + t4]);
                a[mt][2] = fbits(As[(base + gid) * AS_STRIDE + kb + t4 + 4]);
                a[mt][3] = fbits(As[(base + gid + 8) * AS_STRIDE + kb + t4 + 4]);
            }
#pragma unroll
            for (int nt = 0; nt < 8; nt++) {
                uint32_t b0 = fbits(Bs[(kb + t4) * BS_STRIDE + nwb + nt * 8 + gid]);
                uint32_t b1 = fbits(Bs[(kb + t4 + 4) * BS_STRIDE + nwb + nt * 8 + gid]);
                mma_tf32(cacc[0][nt], a[0][0], a[0][1], a[0][2], a[0][3], b0, b1);
                mma_tf32(cacc[1][nt], a[1][0], a[1][1], a[1][2], a[1][3], b0, b1);
            }
        }
    }

    // Epilogue: +bias, cvt tf32, scatter pairs to g_q/g_k/g_v [BH][L][HD]
#pragma unroll
    for (int nt = 0; nt < 8; nt++) {
        int n = n0 + nwb + nt * 8 + 2 * t4;
        float b0 = bias[n], b1 = bias[n + 1];
        int which = n >> 10;
        int rem = n & 1023;
        int h = rem >> 6, hd = rem & 63;
        float* dst = (which == 0) ? g_q : ((which == 1) ? g_k : g_v);
#pragma unroll
        for (int mt = 0; mt < 2; mt++) {
#pragma unroll
            for (int hf = 0; hf < 2; hf++) {
                int m = m0 + mwb + mt * 16 + gid + hf * 8;
                int bb = m >> 10, l = m & 1023;
                float2 v2;
                v2.x = __uint_as_float(f2tf(cacc[mt][nt][hf * 2 + 0] + b0));
                v2.y = __uint_as_float(f2tf(cacc[mt][nt][hf * 2 + 1] + b1));
                *(float2*)(dst + (((size_t)bb * HH + h) * LL + l) * HD + hd) = v2;
            }
        }
    }
}

// ---------------------------------------------------------------------------
// Kernel 2: fused attention, tf32 mma everywhere.
// Block: 64 l-rows x one (b,h); 8 warps; streams 16 r-tiles of 64.
// ---------------------------------------------------------------------------
#define QS 68   // Qs/Ks/Es/S row stride
#define VSS 72  // Vs row stride

struct AttnSmem {
    float Qs[64 * QS];    // [l][d] tf32 bits
    float Ks[64 * QS];    // [r][d] tf32 bits
    float Vs[64 * VSS];   // [r][d] tf32 bits
    float Es[128 * QS];   // [j][d] tf32 bits (row 127 unused)
    float S[64 * QS];     // [l][r] fp32 scores -> P (tf32 bits)
    float fac_s[64];
    float inv_s[64];
};

__global__ __launch_bounds__(256, 1) void attn_kernel(const float* __restrict__ dist_emb,
                                                      float* __restrict__ out) {
    extern __shared__ char smem_raw[];
    AttnSmem& sm = *(AttnSmem*)smem_raw;

    const int t    = threadIdx.x;
    const int lane = t & 31;
    const int wrp  = t >> 5;
    const int gid  = lane >> 2;
    const int t4   = lane & 3;

    const int bh = blockIdx.y;
    const int l0 = blockIdx.x * 64;
    const int b  = bh >> 4;
    const int h  = bh & 15;

    const float* qp = g_q + (size_t)bh * LL * HD;
    const float* kp = g_k + (size_t)bh * LL * HD;
    const float* vp = g_v + (size_t)bh * LL * HD;

    // warp tiling
    const int rW = (wrp & 3) * 16;        // row base (S, QE/KE A-rows, PV)
    const int cS = (wrp >> 2) * 32;       // S / PV col group
    const int cQ = (wrp >> 2) * 64;       // QE/KE col group (j)

    // softmax ownership: thread -> row t>>2, quarter t&3
    const int srow = t >> 2;
    const int sq   = t & 3;

    // Load Q tile (already tf32 bits) : Qs[l][d]
#pragma unroll
    for (int p = 0; p < 4; p++) {
        int f = t + p * 256;
        int l = f >> 4, dg = (f & 15) * 4;
        *(float4*)(&sm.Qs[l * QS + dg]) = *(const float4*)(qp + (size_t)(l0 + l) * HD + dg);
    }

    float o_acc[4][4];
#pragma unroll
    for (int nt = 0; nt < 4; nt++)
#pragma unroll
        for (int e = 0; e < 4; e++) o_acc[nt][e] = 0.f;

    float m_run = -1e30f, s_run = 0.f;

    for (int r0 = 0; r0 < LL; r0 += 64) {
        // ---- loads: K, V (copy tf32), E (cvt) ----
#pragma unroll
        for (int p = 0; p < 4; p++) {
            int f = t + p * 256;
            int r = f >> 4, dg = (f & 15) * 4;
            *(float4*)(&sm.Ks[r * QS + dg]) =
                *(const float4*)(kp + (size_t)(r0 + r) * HD + dg);
            *(float4*)(&sm.Vs[r * VSS + dg]) =
                *(const float4*)(vp + (size_t)(r0 + r) * HD + dg);
        }
        const int jbase = l0 - r0 + 960;
#pragma unroll
        for (int p = 0; p < 8; p++) {
            int f = t + p * 256;
            int j = f >> 4, dg = (f & 15) * 4;
            if (j < 127) {
                float4 e4 = *(const float4*)(dist_emb + (size_t)(jbase + j) * HD + dg);
                float* es = &sm.Es[j * QS + dg];
                es[0] = __uint_as_float(f2tf(e4.x));
                es[1] = __uint_as_float(f2tf(e4.y));
                es[2] = __uint_as_float(f2tf(e4.z));
                es[3] = __uint_as_float(f2tf(e4.w));
            }
        }
        __syncthreads();

        // ---- S = Q K^T (warp tile 16x32) ----
        {
            float sacc[4][4];
#pragma unroll
            for (int nt = 0; nt < 4; nt++)
#pragma unroll
                for (int e = 0; e < 4; e++) sacc[nt][e] = 0.f;
#pragma unroll
            for (int ks = 0; ks < 8; ks++) {
                const int kb = ks * 8;
                uint32_t a0 = fbits(sm.Qs[(rW + gid) * QS + kb + t4]);
                uint32_t a1 = fbits(sm.Qs[(rW + gid + 8) * QS + kb + t4]);
                uint32_t a2 = fbits(sm.Qs[(rW + gid) * QS + kb + t4 + 4]);
                uint32_t a3 = fbits(sm.Qs[(rW + gid + 8) * QS + kb + t4 + 4]);
#pragma unroll
                for (int nt = 0; nt < 4; nt++) {
                    int n0 = cS + nt * 8;
                    uint32_t b0 = fbits(sm.Ks[(n0 + gid) * QS + kb + t4]);
                    uint32_t b1 = fbits(sm.Ks[(n0 + gid) * QS + kb + t4 + 4]);
                    mma_tf32(sacc[nt], a0, a1, a2, a3, b0, b1);
                }
            }
#pragma unroll
            for (int nt = 0; nt < 4; nt++) {
                int c = cS + nt * 8 + 2 * t4;
                *(float2*)(&sm.S[(rW + gid) * QS + c])     = make_float2(sacc[nt][0], sacc[nt][1]);
                *(float2*)(&sm.S[(rW + gid + 8) * QS + c]) = make_float2(sacc[nt][2], sacc[nt][3]);
            }
        }

        // ---- QE = Q E^T (warp tile 16x64), computed before the sync ----
        float qacc[8][4];
#pragma unroll
        for (int nt = 0; nt < 8; nt++)
#pragma unroll
            for (int e = 0; e < 4; e++) qacc[nt][e] = 0.f;
#pragma unroll
        for (int ks = 0; ks < 8; ks++) {
            const int kb = ks * 8;
            uint32_t a0 = fbits(sm.Qs[(rW + gid) * QS + kb + t4]);
            uint32_t a1 = fbits(sm.Qs[(rW + gid + 8) * QS + kb + t4]);
            uint32_t a2 = fbits(sm.Qs[(rW + gid) * QS + kb + t4 + 4]);
            uint32_t a3 = fbits(sm.Qs[(rW + gid + 8) * QS + kb + t4 + 4]);
#pragma unroll
            for (int nt = 0; nt < 8; nt++) {
                int n0 = cQ + nt * 8;
                uint32_t b0 = fbits(sm.Es[(n0 + gid) * QS + kb + t4]);
                uint32_t b1 = fbits(sm.Es[(n0 + gid) * QS + kb + t4 + 4]);
                mma_tf32(qacc[nt], a0, a1, a2, a3, b0, b1);
            }
        }
        __syncthreads();   // S base stores visible

        // ---- scatter QE: (l, j) -> S[l][r], r = l - j + 63 ----
#pragma unroll
        for (int nt = 0; nt < 8; nt++) {
            int jc = cQ + nt * 8 + 2 * t4;
#pragma unroll
            for (int e = 0; e < 4; e++) {
                int l = rW + gid + ((e >> 1) << 3);
                int j = jc + (e & 1);
                int r = l - j + 63;
                if ((unsigned)r < 64u) atomicAdd(&sm.S[l * QS + r], qacc[nt][e]);
            }
        }

        // ---- KE = K E^T, scatter (r, j) -> S[l][r], l = r + j - 63 ----
#pragma unroll
        for (int nt = 0; nt < 8; nt++)
#pragma unroll
            for (int e = 0; e < 4; e++) qacc[nt][e] = 0.f;
#pragma unroll
        for (int ks = 0; ks < 8; ks++) {
            const int kb = ks * 8;
            uint32_t a0 = fbits(sm.Ks[(rW + gid) * QS + kb + t4]);
            uint32_t a1 = fbits(sm.Ks[(rW + gid + 8) * QS + kb + t4]);
            uint32_t a2 = fbits(sm.Ks[(rW + gid) * QS + kb + t4 + 4]);
            uint32_t a3 = fbits(sm.Ks[(rW + gid + 8) * QS + kb + t4 + 4]);
#pragma unroll
            for (int nt = 0; nt < 8; nt++) {
                int n0 = cQ + nt * 8;
                uint32_t b0 = fbits(sm.Es[(n0 + gid) * QS + kb + t4]);
                uint32_t b1 = fbits(sm.Es[(n0 + gid) * QS + kb + t4 + 4]);
                mma_tf32(qacc[nt], a0, a1, a2, a3, b0, b1);
            }
        }
#pragma unroll
        for (int nt = 0; nt < 8; nt++) {
            int jc = cQ + nt * 8 + 2 * t4;
#pragma unroll
            for (int e = 0; e < 4; e++) {
                int r = rW + gid + ((e >> 1) << 3);
                int j = jc + (e & 1);
                int l = r + j - 63;
                if ((unsigned)l < 64u) atomicAdd(&sm.S[l * QS + r], qacc[nt][e]);
            }
        }
        __syncthreads();   // all bias adds done

        // ---- online softmax (4 threads per row, stride-4 columns) ----
        {
            float sv[16];
            float pm = -1e30f;
#pragma unroll
            for (int i = 0; i < 16; i++) {
                sv[i] = sm.S[srow * QS + sq + 4 * i] * SCALE;
                pm = fmaxf(pm, sv[i]);
            }
            pm = fmaxf(pm, __shfl_xor_sync(0xffffffffu, pm, 1));
            pm = fmaxf(pm, __shfl_xor_sync(0xffffffffu, pm, 2));
            float mn = fmaxf(m_run, pm);
            float fac = __expf(m_run - mn);
            m_run = mn;
            float ps = 0.f;
#pragma unroll
            for (int i = 0; i < 16; i++) {
                float pv = __expf(sv[i] - mn);
                ps += pv;
                sm.S[srow * QS + sq + 4 * i] = __uint_as_float(f2tf(pv));
            }
            ps += __shfl_xor_sync(0xffffffffu, ps, 1);
            ps += __shfl_xor_sync(0xffffffffu, ps, 2);
            s_run = s_run * fac + ps;
            if (sq == 0) sm.fac_s[srow] = fac;
        }
        __syncthreads();   // P + fac ready

        // ---- rescale O, then O += P V ----
        {
            float f0 = sm.fac_s[rW + gid];
            float f1 = sm.fac_s[rW + gid + 8];
#pragma unroll
            for (int nt = 0; nt < 4; nt++) {
                o_acc[nt][0] *= f0; o_acc[nt][1] *= f0;
                o_acc[nt][2] *= f1; o_acc[nt][3] *= f1;
            }
#pragma unroll
            for (int ks = 0; ks < 8; ks++) {
                const int kb = ks * 8;
                uint32_t a0 = fbits(sm.S[(rW + gid) * QS + kb + t4]);
                uint32_t a1 = fbits(sm.S[(rW + gid + 8) * QS + kb + t4]);
                uint32_t a2 = fbits(sm.S[(rW + gid) * QS + kb + t4 + 4]);
                uint32_t a3 = fbits(sm.S[(rW + gid + 8) * QS + kb + t4 + 4]);
#pragma unroll
                for (int nt = 0; nt < 4; nt++) {
                    int n0 = cS + nt * 8;
                    uint32_t b0 = fbits(sm.Vs[(kb + t4) * VSS + n0 + gid]);
                    uint32_t b1 = fbits(sm.Vs[(kb + t4 + 4) * VSS + n0 + gid]);
                    mma_tf32(o_acc[nt], a0, a1, a2, a3, b0, b1);
                }
            }
        }
        __syncthreads();   // end of iter: smem free for next loads
    }

    if (sq == 0) sm.inv_s[srow] = 1.f / s_run;
    __syncthreads();

    // ---- epilogue: O / sum -> out[B,L,D] ----
    {
        float i0 = sm.inv_s[rW + gid];
        float i1 = sm.inv_s[rW + gid + 8];
        int lg0 = l0 + rW + gid;
        int lg1 = lg0 + 8;
#pragma unroll
        for (int nt = 0; nt < 4; nt++) {
            int c = cS + nt * 8 + 2 * t4;
            float2 v0 = make_float2(o_acc[nt][0] * i0, o_acc[nt][1] * i0);
            float2 v1 = make_float2(o_acc[nt][2] * i1, o_acc[nt][3] * i1);
            *(float2*)(out + ((size_t)b * LL + lg0) * DD + h * HD + c) = v0;
            *(float2*)(out + ((size_t)b * LL + lg1) * DD + h * HD + c) = v1;
        }
    }
}

// ---------------------------------------------------------------------------
extern "C" void kernel_launch(void* const* d_in, const int* in_sizes, int n_in,
                              void* d_out, int out_size) {
    const float* x        = (const float*)d_in[0];
    const float* Wqkv     = (const float*)d_in[1];
    const float* bqkv     = (const float*)d_in[2];
    const float* dist_emb = (const float*)d_in[3];
    float* out = (float*)d_out;

    (void)in_sizes; (void)n_in; (void)out_size;

    cudaFuncSetAttribute(attn_kernel, cudaFuncAttributeMaxDynamicSharedMemorySize,
                         (int)sizeof(AttnSmem));

    qkv_kernel<<<dim3(24, 32), 256>>>(x, Wqkv, bqkv);
    attn_kernel<<<dim3(16, 64), 256, sizeof(AttnSmem)>>>(dist_emb, out);
}

// round 4
// speedup vs baseline: 3.1227x; 1.0997x over previous
#include <cuda_runtime.h>
#include <cstdint>

#define BB 4
#define LL 1024
#define DD 1024
#define HH 16
#define HD 64
#define BH (BB*HH)
#define SCALE 0.125f

// q/k stored tf32-bit + k-pair-permuted within 8; v natural tf32-bit. [BH][L][HD]
__device__ float g_q[BH * LL * HD];
__device__ float g_k[BH * LL * HD];
__device__ float g_v[BH * LL * HD];

__device__ __forceinline__ uint32_t f2tf(float f) {
    uint32_t u;
    asm("cvt.rna.tf32.f32 %0, %1;" : "=r"(u) : "f"(f));
    return u;
}
__device__ __forceinline__ uint32_t fbits(float f) { return __float_as_uint(f); }
__device__ __forceinline__ int perm8(int k) {
    return (k & ~7) | (((k & 3) << 1) | ((k >> 2) & 1));
}

__device__ __forceinline__ void mma_tf32(float c[4], uint32_t a0, uint32_t a1,
                                         uint32_t a2, uint32_t a3,
                                         uint32_t b0, uint32_t b1) {
    asm volatile(
        "mma.sync.aligned.m16n8k8.row.col.f32.tf32.tf32.f32 "
        "{%0,%1,%2,%3},{%4,%5,%6,%7},{%8,%9},{%0,%1,%2,%3};"
        : "+f"(c[0]), "+f"(c[1]), "+f"(c[2]), "+f"(c[3])
        : "r"(a0), "r"(a1), "r"(a2), "r"(a3), "r"(b0), "r"(b1));
}

// ---------------------------------------------------------------------------
// Kernel 1: QKV projection with tf32 mma. C[4096,3072] = x @ W + b.
// ---------------------------------------------------------------------------
#define AS_STRIDE 20
#define BS_STRIDE 136

__global__ __launch_bounds__(256) void qkv_kernel(const float* __restrict__ x,
                                                  const float* __restrict__ w,
                                                  const float* __restrict__ bias) {
    __shared__ float As[128 * AS_STRIDE];   // [m][k] tf32 bits
    __shared__ float Bs[16 * BS_STRIDE];    // [k][n] tf32 bits

    const int t    = threadIdx.x;
    const int lane = t & 31;
    const int wrp  = t >> 5;
    const int gid  = lane >> 2;
    const int t4   = lane & 3;
    const int m0 = blockIdx.y * 128;
    const int n0 = blockIdx.x * 128;
    const int mwb = (wrp & 3) * 32;
    const int nwb = (wrp >> 2) * 64;

    float cacc[2][8][4];
#pragma unroll
    for (int mt = 0; mt < 2; mt++)
#pragma unroll
        for (int nt = 0; nt < 8; nt++)
#pragma unroll
            for (int e = 0; e < 4; e++) cacc[mt][nt][e] = 0.f;

    int xrow[2], xk[2], wrow[2], wn[2];
#pragma unroll
    for (int p = 0; p < 2; p++) {
        int f = t + p * 256;
        xrow[p] = f >> 2;  xk[p] = (f & 3) * 4;       // 128 rows x 16 k
        wrow[p] = f >> 5;  wn[p] = (f & 31) * 4;      // 16 k x 128 n
    }

    float4 xa[2], wb[2];
#pragma unroll
    for (int p = 0; p < 2; p++) {
        xa[p] = *(const float4*)(x + (size_t)(m0 + xrow[p]) * 1024 + 0 + xk[p]);
        wb[p] = *(const float4*)(w + (size_t)(0 + wrow[p]) * 3072 + n0 + wn[p]);
    }

    for (int k0 = 0; k0 < 1024; k0 += 16) {
        __syncthreads();
#pragma unroll
        for (int p = 0; p < 2; p++) {
            float* a = &As[xrow[p] * AS_STRIDE + xk[p]];
            a[0] = __uint_as_float(f2tf(xa[p].x));
            a[1] = __uint_as_float(f2tf(xa[p].y));
            a[2] = __uint_as_float(f2tf(xa[p].z));
            a[3] = __uint_as_float(f2tf(xa[p].w));
            float* bq = &Bs[wrow[p] * BS_STRIDE + wn[p]];
            bq[0] = __uint_as_float(f2tf(wb[p].x));
            bq[1] = __uint_as_float(f2tf(wb[p].y));
            bq[2] = __uint_as_float(f2tf(wb[p].z));
            bq[3] = __uint_as_float(f2tf(wb[p].w));
        }
        __syncthreads();
        if (k0 + 16 < 1024) {
#pragma unroll
            for (int p = 0; p < 2; p++) {
                xa[p] = *(const float4*)(x + (size_t)(m0 + xrow[p]) * 1024 + (k0 + 16) + xk[p]);
                wb[p] = *(const float4*)(w + (size_t)((k0 + 16) + wrow[p]) * 3072 + n0 + wn[p]);
            }
        }
#pragma unroll
        for (int ks = 0; ks < 2; ks++) {
            const int kb = ks * 8;
            uint32_t a[2][4];
#pragma unroll
            for (int mt = 0; mt < 2; mt++) {
                int base = mwb + mt * 16;
                a[mt][0] = fbits(As[(base + gid) * AS_STRIDE + kb + t4]);
                a[mt][1] = fbits(As[(base + gid + 8) * AS_STRIDE + kb + t4]);
                a[mt][2] = fbits(As[(base + gid) * AS_STRIDE + kb + t4 + 4]);
                a[mt][3] = fbits(As[(base + gid + 8) * AS_STRIDE + kb + t4 + 4]);
            }
#pragma unroll
            for (int nt = 0; nt < 8; nt++) {
                uint32_t b0 = fbits(Bs[(kb + t4) * BS_STRIDE + nwb + nt * 8 + gid]);
                uint32_t b1 = fbits(Bs[(kb + t4 + 4) * BS_STRIDE + nwb + nt * 8 + gid]);
                mma_tf32(cacc[0][nt], a[0][0], a[0][1], a[0][2], a[0][3], b0, b1);
                mma_tf32(cacc[1][nt], a[1][0], a[1][1], a[1][2], a[1][3], b0, b1);
            }
        }
    }

    // Epilogue: +bias, cvt tf32; q/k stored PERMUTED within 8-col blocks, v natural.
#pragma unroll
    for (int nt = 0; nt < 8; nt++) {
        int n = n0 + nwb + nt * 8 + 2 * t4;      // even
        float b0 = bias[n], b1 = bias[n + 1];
        int which = n >> 10;
        int rem = n & 1023;
        int h = rem >> 6, hd = rem & 63;
        float* dst = (which == 0) ? g_q : ((which == 1) ? g_k : g_v);
        int p0 = perm8(hd);                      // hd even -> pair at p0, p0+2
#pragma unroll
        for (int mt = 0; mt < 2; mt++) {
#pragma unroll
            for (int hf = 0; hf < 2; hf++) {
                int m = m0 + mwb + mt * 16 + gid + hf * 8;
                int bb = m >> 10, l = m & 1023;
                float v0 = __uint_as_float(f2tf(cacc[mt][nt][hf * 2 + 0] + b0));
                float v1 = __uint_as_float(f2tf(cacc[mt][nt][hf * 2 + 1] + b1));
                float* row = dst + (((size_t)bb * HH + h) * LL + l) * HD;
                if (which == 2) {
                    *(float2*)(row + hd) = make_float2(v0, v1);
                } else {
                    row[p0]     = v0;
                    row[p0 + 2] = v1;
                }
            }
        }
    }
}

// ---------------------------------------------------------------------------
// Kernel 2: fused attention, tf32 mma, paired-LDS layout, banded QE/KE.
// ---------------------------------------------------------------------------
#define QS 72   // unified row stride (8 mod 32 -> conflict-free paired loads)

struct AttnSmem {
    float Qs[64 * QS];    // [l][perm(d)]
    float Ks[64 * QS];    // [r][perm(d)]
    float Vs[64 * QS];    // [r][d] natural
    float Es[128 * QS];   // [j][perm(d)] (row 127 unread)
    float S[64 * QS];     // [l][perm(r)] scores -> P
    float fac_s[64];
    float inv_s[64];
};

__global__ __launch_bounds__(256, 1) void attn_kernel(const float* __restrict__ dist_emb,
                                                      float* __restrict__ out) {
    extern __shared__ char smem_raw[];
    AttnSmem& sm = *(AttnSmem*)smem_raw;

    const int t    = threadIdx.x;
    const int lane = t & 31;
    const int wrp  = t >> 5;
    const int gid  = lane >> 2;
    const int t4   = lane & 3;

    const int bh = blockIdx.y;
    const int l0 = blockIdx.x * 64;
    const int b  = bh >> 4;
    const int h  = bh & 15;

    const float* qp = g_q + (size_t)bh * LL * HD;
    const float* kp = g_k + (size_t)bh * LL * HD;
    const float* vp = g_v + (size_t)bh * LL * HD;

    const int rW = (wrp & 3) * 16;        // row group base
    const int hh = wrp >> 2;              // column half
    const int cS = hh * 32;               // S / PV col group
    const int jtQ = (rW >> 3) + 5 * hh;       // QE band tile base (5 tiles)
    const int jtK = (6 - (rW >> 3)) + 5 * hh; // KE band tile base (5 tiles)
    const int pg  = ((gid & 3) << 1) | (gid >> 2);  // perm low bits of gid

    const int srow = t >> 2;              // softmax row
    const int sq   = t & 3;               // softmax quarter

    // Load Q tile (already permuted tf32 bits)
#pragma unroll
    for (int p = 0; p < 4; p++) {
        int f = t + p * 256;
        int l = f >> 4, dg = (f & 15) * 4;
        *(float4*)(&sm.Qs[l * QS + dg]) = *(const float4*)(qp + (size_t)(l0 + l) * HD + dg);
    }

    float o_acc[4][4];
#pragma unroll
    for (int nt = 0; nt < 4; nt++)
#pragma unroll
        for (int e = 0; e < 4; e++) o_acc[nt][e] = 0.f;

    float m_run = -1e30f, s_run = 0.f;

    for (int r0 = 0; r0 < LL; r0 += 64) {
        // ---- loads: K (permuted bits), V (natural), E (cvt+permute) ----
#pragma unroll
        for (int p = 0; p < 4; p++) {
            int f = t + p * 256;
            int r = f >> 4, dg = (f & 15) * 4;
            *(float4*)(&sm.Ks[r * QS + dg]) =
                *(const float4*)(kp + (size_t)(r0 + r) * HD + dg);
            *(float4*)(&sm.Vs[r * QS + dg]) =
                *(const float4*)(vp + (size_t)(r0 + r) * HD + dg);
        }
        const int jbase = l0 - r0 + 960;
#pragma unroll
        for (int p = 0; p < 8; p++) {
            int f = t + p * 256;
            int j = f >> 4, dg = (f & 15) * 4;
            if (j < 127) {
                float4 e4 = *(const float4*)(dist_emb + (size_t)(jbase + j) * HD + dg);
                float* es = &sm.Es[j * QS + ((dg & ~7) | ((dg >> 2) & 1))];
                es[0] = __uint_as_float(f2tf(e4.x));
                es[2] = __uint_as_float(f2tf(e4.y));
                es[4] = __uint_as_float(f2tf(e4.z));
                es[6] = __uint_as_float(f2tf(e4.w));
            }
        }
        __syncthreads();

        // ---- S = Q K^T  and  QE = Q E^T (banded), shared A fragments ----
        float sacc[4][4], qacc[5][4];
#pragma unroll
        for (int nt = 0; nt < 4; nt++)
#pragma unroll
            for (int e = 0; e < 4; e++) sacc[nt][e] = 0.f;
#pragma unroll
        for (int tt = 0; tt < 5; tt++)
#pragma unroll
            for (int e = 0; e < 4; e++) qacc[tt][e] = 0.f;

#pragma unroll
        for (int ks = 0; ks < 8; ks++) {
            const int ka = ks * 8 + 2 * t4;
            float2 aL = *(const float2*)(&sm.Qs[(rW + gid) * QS + ka]);
            float2 aH = *(const float2*)(&sm.Qs[(rW + gid + 8) * QS + ka]);
            uint32_t a0 = fbits(aL.x), a1 = fbits(aH.x);
            uint32_t a2 = fbits(aL.y), a3 = fbits(aH.y);
#pragma unroll
            for (int nt = 0; nt < 4; nt++) {
                float2 bb = *(const float2*)(&sm.Ks[(cS + nt * 8 + gid) * QS + ka]);
                mma_tf32(sacc[nt], a0, a1, a2, a3, fbits(bb.x), fbits(bb.y));
            }
#pragma unroll
            for (int tt = 0; tt < 5; tt++) {
                float2 bb = *(const float2*)(&sm.Es[((jtQ + tt) * 8 + gid) * QS + ka]);
                mma_tf32(qacc[tt], a0, a1, a2, a3, fbits(bb.x), fbits(bb.y));
            }
        }
        // store S (scalar, permuted columns)
#pragma unroll
        for (int nt = 0; nt < 4; nt++) {
            int c = cS + nt * 8 + 2 * t4;
            int p0 = perm8(c);
            sm.S[(rW + gid) * QS + p0]         = sacc[nt][0];
            sm.S[(rW + gid) * QS + p0 + 2]     = sacc[nt][1];
            sm.S[(rW + gid + 8) * QS + p0]     = sacc[nt][2];
            sm.S[(rW + gid + 8) * QS + p0 + 2] = sacc[nt][3];
        }
        __syncthreads();

        // ---- scatter QE: (l, j) -> S[l][perm(r)], r = l - j + 63 ----
#pragma unroll
        for (int tt = 0; tt < 5; tt++) {
            int jc = (jtQ + tt) * 8 + 2 * t4;
#pragma unroll
            for (int e = 0; e < 4; e++) {
                int l = rW + gid + ((e >> 1) << 3);
                int j = jc + (e & 1);
                int r = l - j + 63;
                if ((unsigned)r < 64u) atomicAdd(&sm.S[l * QS + perm8(r)], qacc[tt][e]);
            }
        }

        // ---- KE = K E^T (banded) ----
        float kacc[5][4];
#pragma unroll
        for (int tt = 0; tt < 5; tt++)
#pragma unroll
            for (int e = 0; e < 4; e++) kacc[tt][e] = 0.f;
#pragma unroll
        for (int ks = 0; ks < 8; ks++) {
            const int ka = ks * 8 + 2 * t4;
            float2 aL = *(const float2*)(&sm.Ks[(rW + gid) * QS + ka]);
            float2 aH = *(const float2*)(&sm.Ks[(rW + gid + 8) * QS + ka]);
            uint32_t a0 = fbits(aL.x), a1 = fbits(aH.x);
            uint32_t a2 = fbits(aL.y), a3 = fbits(aH.y);
#pragma unroll
            for (int tt = 0; tt < 5; tt++) {
                float2 bb = *(const float2*)(&sm.Es[((jtK + tt) * 8 + gid) * QS + ka]);
                mma_tf32(kacc[tt], a0, a1, a2, a3, fbits(bb.x), fbits(bb.y));
            }
        }
        // scatter KE: (r, j) -> S[l][perm(r)], l = r + j - 63
#pragma unroll
        for (int tt = 0; tt < 5; tt++) {
            int jc = (jtK + tt) * 8 + 2 * t4;
#pragma unroll
            for (int e = 0; e < 4; e++) {
                int rb = (e >> 1) << 3;
                int r = rW + gid + rb;
                int j = jc + (e & 1);
                int l = r + j - 63;
                if ((unsigned)l < 64u)
                    atomicAdd(&sm.S[l * QS + rW + rb + pg], kacc[tt][e]);
            }
        }
        __syncthreads();

        // ---- online softmax: 4 threads/row, 16 contiguous slots each ----
        {
            float4 sv[4];
            float pm = -1e30f;
#pragma unroll
            for (int i = 0; i < 4; i++) {
                sv[i] = *(const float4*)(&sm.S[srow * QS + sq * 16 + 4 * i]);
                sv[i].x *= SCALE; sv[i].y *= SCALE; sv[i].z *= SCALE; sv[i].w *= SCALE;
                pm = fmaxf(pm, fmaxf(fmaxf(sv[i].x, sv[i].y), fmaxf(sv[i].z, sv[i].w)));
            }
            pm = fmaxf(pm, __shfl_xor_sync(0xffffffffu, pm, 1));
            pm = fmaxf(pm, __shfl_xor_sync(0xffffffffu, pm, 2));
            float mn = fmaxf(m_run, pm);
            float fac = __expf(m_run - mn);
            m_run = mn;
            float ps = 0.f;
#pragma unroll
            for (int i = 0; i < 4; i++) {
                float4 pv;
                pv.x = __expf(sv[i].x - mn); pv.y = __expf(sv[i].y - mn);
                pv.z = __expf(sv[i].z - mn); pv.w = __expf(sv[i].w - mn);
                ps += (pv.x + pv.y) + (pv.z + pv.w);
                float4 pb;
                pb.x = __uint_as_float(f2tf(pv.x)); pb.y = __uint_as_float(f2tf(pv.y));
                pb.z = __uint_as_float(f2tf(pv.z)); pb.w = __uint_as_float(f2tf(pv.w));
                *(float4*)(&sm.S[srow * QS + sq * 16 + 4 * i]) = pb;
            }
            ps += __shfl_xor_sync(0xffffffffu, ps, 1);
            ps += __shfl_xor_sync(0xffffffffu, ps, 2);
            s_run = s_run * fac + ps;
            if (sq == 0) sm.fac_s[srow] = fac;
        }
        __syncthreads();

        // ---- rescale O, then O += P V ----
        {
            float f0 = sm.fac_s[rW + gid];
            float f1 = sm.fac_s[rW + gid + 8];
#pragma unroll
            for (int nt = 0; nt < 4; nt++) {
                o_acc[nt][0] *= f0; o_acc[nt][1] *= f0;
                o_acc[nt][2] *= f1; o_acc[nt][3] *= f1;
            }
#pragma unroll
            for (int ks = 0; ks < 8; ks++) {
                const int ka = ks * 8 + 2 * t4;
                float2 aL = *(const float2*)(&sm.S[(rW + gid) * QS + ka]);
                float2 aH = *(const float2*)(&sm.S[(rW + gid + 8) * QS + ka]);
                uint32_t a0 = fbits(aL.x), a1 = fbits(aH.x);
                uint32_t a2 = fbits(aL.y), a3 = fbits(aH.y);
#pragma unroll
                for (int nt = 0; nt < 4; nt++) {
                    int n0 = cS + nt * 8 + gid;
                    uint32_t b0 = fbits(sm.Vs[(ks * 8 + t4) * QS + n0]);
                    uint32_t b1 = fbits(sm.Vs[(ks * 8 + t4 + 4) * QS + n0]);
                    mma_tf32(o_acc[nt], a0, a1, a2, a3, b0, b1);
                }
            }
        }
        __syncthreads();
    }

    if (sq == 0) sm.inv_s[srow] = 1.f / s_run;
    __syncthreads();

    // ---- epilogue ----
    {
        float i0 = sm.inv_s[rW + gid];
        float i1 = sm.inv_s[rW + gid + 8];
        int lg0 = l0 + rW + gid;
        int lg1 = lg0 + 8;
#pragma unroll
        for (int nt = 0; nt < 4; nt++) {
            int c = cS + nt * 8 + 2 * t4;
            float2 v0 = make_float2(o_acc[nt][0] * i0, o_acc[nt][1] * i0);
            float2 v1 = make_float2(o_acc[nt][2] * i1, o_acc[nt][3] * i1);
            *(float2*)(out + ((size_t)b * LL + lg0) * DD + h * HD + c) = v0;
            *(float2*)(out + ((size_t)b * LL + lg1) * DD + h * HD + c) = v1;
        }
    }
}

// ---------------------------------------------------------------------------
extern "C" void kernel_launch(void* const* d_in, const int* in_sizes, int n_in,
                              void* d_out, int out_size) {
    const float* x        = (const float*)d_in[0];
    const float* Wqkv     = (const float*)d_in[1];
    const float* bqkv     = (const float*)d_in[2];
    const float* dist_emb = (const float*)d_in[3];
    float* out = (float*)d_out;

    (void)in_sizes; (void)n_in; (void)out_size;

    cudaFuncSetAttribute(attn_kernel, cudaFuncAttributeMaxDynamicSharedMemorySize,
                         (int)sizeof(AttnSmem));

    qkv_kernel<<<dim3(24, 32), 256>>>(x, Wqkv, bqkv);
    attn_kernel<<<dim3(16, 64), 256, sizeof(AttnSmem)>>>(dist_emb, out);
}

// round 5
// speedup vs baseline: 3.4277x; 1.0976x over previous
#include <cuda_runtime.h>
#include <cstdint>

#define BB 4
#define LL 1024
#define DD 1024
#define HH 16
#define HD 64
#define BH (BB*HH)
#define SCALE 0.125f

// q/k stored tf32-bit + k-pair-permuted within 8; v natural tf32-bit. [BH][L][HD]
__device__ float g_q[BH * LL * HD];
__device__ float g_k[BH * LL * HD];
__device__ float g_v[BH * LL * HD];
// dist_emb, tf32-cvt'd + permuted rows: [2047][64]
__device__ float g_e[2047 * HD];

__device__ __forceinline__ uint32_t f2tf(float f) {
    uint32_t u;
    asm("cvt.rna.tf32.f32 %0, %1;" : "=r"(u) : "f"(f));
    return u;
}
__device__ __forceinline__ uint32_t fbits(float f) { return __float_as_uint(f); }
__device__ __forceinline__ int perm8(int k) {
    return (k & ~7) | (((k & 3) << 1) | ((k >> 2) & 1));
}
__device__ __forceinline__ void cp16(uint32_t dst, const void* src) {
    asm volatile("cp.async.ca.shared.global [%0], [%1], 16;" :: "r"(dst), "l"(src));
}
__device__ __forceinline__ void cp_commit() {
    asm volatile("cp.async.commit_group;");
}
template <int N>
__device__ __forceinline__ void cp_wait() {
    asm volatile("cp.async.wait_group %0;" :: "n"(N));
}

__device__ __forceinline__ void mma_tf32(float c[4], uint32_t a0, uint32_t a1,
                                         uint32_t a2, uint32_t a3,
                                         uint32_t b0, uint32_t b1) {
    asm volatile(
        "mma.sync.aligned.m16n8k8.row.col.f32.tf32.tf32.f32 "
        "{%0,%1,%2,%3},{%4,%5,%6,%7},{%8,%9},{%0,%1,%2,%3};"
        : "+f"(c[0]), "+f"(c[1]), "+f"(c[2]), "+f"(c[3])
        : "r"(a0), "r"(a1), "r"(a2), "r"(a3), "r"(b0), "r"(b1));
}

// ---------------------------------------------------------------------------
// Kernel 0: convert dist_emb -> tf32 bits, k-pair permuted rows.
// ---------------------------------------------------------------------------
__global__ __launch_bounds__(256) void prep_e_kernel(const float* __restrict__ dist_emb) {
    int idx = blockIdx.x * 256 + threadIdx.x;
    if (idx < 2047 * HD) {
        int j = idx >> 6, d = idx & 63;
        g_e[j * HD + perm8(d)] = __uint_as_float(f2tf(dist_emb[idx]));
    }
}

// ---------------------------------------------------------------------------
// Kernel 1: QKV projection with tf32 mma. C[4096,3072] = x @ W + b.
// ---------------------------------------------------------------------------
#define AS_STRIDE 20
#define BS_STRIDE 136

__global__ __launch_bounds__(256) void qkv_kernel(const float* __restrict__ x,
                                                  const float* __restrict__ w,
                                                  const float* __restrict__ bias) {
    __shared__ float As[128 * AS_STRIDE];   // [m][k] tf32 bits
    __shared__ float Bs[16 * BS_STRIDE];    // [k][n] tf32 bits

    const int t    = threadIdx.x;
    const int lane = t & 31;
    const int wrp  = t >> 5;
    const int gid  = lane >> 2;
    const int t4   = lane & 3;
    const int m0 = blockIdx.y * 128;
    const int n0 = blockIdx.x * 128;
    const int mwb = (wrp & 3) * 32;
    const int nwb = (wrp >> 2) * 64;

    float cacc[2][8][4];
#pragma unroll
    for (int mt = 0; mt < 2; mt++)
#pragma unroll
        for (int nt = 0; nt < 8; nt++)
#pragma unroll
            for (int e = 0; e < 4; e++) cacc[mt][nt][e] = 0.f;

    int xrow[2], xk[2], wrow[2], wn[2];
#pragma unroll
    for (int p = 0; p < 2; p++) {
        int f = t + p * 256;
        xrow[p] = f >> 2;  xk[p] = (f & 3) * 4;       // 128 rows x 16 k
        wrow[p] = f >> 5;  wn[p] = (f & 31) * 4;      // 16 k x 128 n
    }

    float4 xa[2], wb[2];
#pragma unroll
    for (int p = 0; p < 2; p++) {
        xa[p] = *(const float4*)(x + (size_t)(m0 + xrow[p]) * 1024 + 0 + xk[p]);
        wb[p] = *(const float4*)(w + (size_t)(0 + wrow[p]) * 3072 + n0 + wn[p]);
    }

    for (int k0 = 0; k0 < 1024; k0 += 16) {
        __syncthreads();
#pragma unroll
        for (int p = 0; p < 2; p++) {
            float* a = &As[xrow[p] * AS_STRIDE + xk[p]];
            a[0] = __uint_as_float(f2tf(xa[p].x));
            a[1] = __uint_as_float(f2tf(xa[p].y));
            a[2] = __uint_as_float(f2tf(xa[p].z));
            a[3] = __uint_as_float(f2tf(xa[p].w));
            float* bq = &Bs[wrow[p] * BS_STRIDE + wn[p]];
            bq[0] = __uint_as_float(f2tf(wb[p].x));
            bq[1] = __uint_as_float(f2tf(wb[p].y));
            bq[2] = __uint_as_float(f2tf(wb[p].z));
            bq[3] = __uint_as_float(f2tf(wb[p].w));
        }
        __syncthreads();
        if (k0 + 16 < 1024) {
#pragma unroll
            for (int p = 0; p < 2; p++) {
                xa[p] = *(const float4*)(x + (size_t)(m0 + xrow[p]) * 1024 + (k0 + 16) + xk[p]);
                wb[p] = *(const float4*)(w + (size_t)((k0 + 16) + wrow[p]) * 3072 + n0 + wn[p]);
            }
        }
#pragma unroll
        for (int ks = 0; ks < 2; ks++) {
            const int kb = ks * 8;
            uint32_t a[2][4];
#pragma unroll
            for (int mt = 0; mt < 2; mt++) {
                int base = mwb + mt * 16;
                a[mt][0] = fbits(As[(base + gid) * AS_STRIDE + kb + t4]);
                a[mt][1] = fbits(As[(base + gid + 8) * AS_STRIDE + kb + t4]);
                a[mt][2] = fbits(As[(base + gid) * AS_STRIDE + kb + t4 + 4]);
                a[mt][3] = fbits(As[(base + gid + 8) * AS_STRIDE + kb + t4 + 4]);
            }
#pragma unroll
            for (int nt = 0; nt < 8; nt++) {
                uint32_t b0 = fbits(Bs[(kb + t4) * BS_STRIDE + nwb + nt * 8 + gid]);
                uint32_t b1 = fbits(Bs[(kb + t4 + 4) * BS_STRIDE + nwb + nt * 8 + gid]);
                mma_tf32(cacc[0][nt], a[0][0], a[0][1], a[0][2], a[0][3], b0, b1);
                mma_tf32(cacc[1][nt], a[1][0], a[1][1], a[1][2], a[1][3], b0, b1);
            }
        }
    }

    // Epilogue: +bias, cvt tf32; q/k stored PERMUTED within 8-col blocks, v natural.
#pragma unroll
    for (int nt = 0; nt < 8; nt++) {
        int n = n0 + nwb + nt * 8 + 2 * t4;      // even
        float b0 = bias[n], b1 = bias[n + 1];
        int which = n >> 10;
        int rem = n & 1023;
        int h = rem >> 6, hd = rem & 63;
        float* dst = (which == 0) ? g_q : ((which == 1) ? g_k : g_v);
        int p0 = perm8(hd);                      // hd even -> pair at p0, p0+2
#pragma unroll
        for (int mt = 0; mt < 2; mt++) {
#pragma unroll
            for (int hf = 0; hf < 2; hf++) {
                int m = m0 + mwb + mt * 16 + gid + hf * 8;
                int bb = m >> 10, l = m & 1023;
                float v0 = __uint_as_float(f2tf(cacc[mt][nt][hf * 2 + 0] + b0));
                float v1 = __uint_as_float(f2tf(cacc[mt][nt][hf * 2 + 1] + b1));
                float* row = dst + (((size_t)bb * HH + h) * LL + l) * HD;
                if (which == 2) {
                    *(float2*)(row + hd) = make_float2(v0, v1);
                } else {
                    row[p0]     = v0;
                    row[p0 + 2] = v1;
                }
            }
        }
    }
}

// ---------------------------------------------------------------------------
// Kernel 2: fused attention, tf32 mma, paired-LDS layout, banded QE/KE,
// cp.async double-buffered K/V/E.
// ---------------------------------------------------------------------------
#define QS 72   // unified row stride (8 mod 32 -> conflict-free paired loads)

struct AttnSmem {
    float Qs[64 * QS];       // [l][perm(d)]
    float Ks[2][64 * QS];    // [r][perm(d)]
    float Vs[2][64 * QS];    // [r][d] natural
    float Es[2][128 * QS];   // [j][perm(d)] (row 127 never written/used)
    float S[64 * QS];        // [l][perm(r)] scores -> P
    float fac_s[64];
    float inv_s[64];
};

__global__ __launch_bounds__(256, 1) void attn_kernel(float* __restrict__ out) {
    extern __shared__ char smem_raw[];
    AttnSmem& sm = *(AttnSmem*)smem_raw;

    const int t    = threadIdx.x;
    const int lane = t & 31;
    const int wrp  = t >> 5;
    const int gid  = lane >> 2;
    const int t4   = lane & 3;

    const int bh = blockIdx.y;
    const int l0 = blockIdx.x * 64;
    const int b  = bh >> 4;
    const int h  = bh & 15;

    const float* qp = g_q + (size_t)bh * LL * HD;
    const float* kp = g_k + (size_t)bh * LL * HD;
    const float* vp = g_v + (size_t)bh * LL * HD;

    const int rW = (wrp & 3) * 16;        // row group base
    const int hh = wrp >> 2;              // column half
    const int cS = hh * 32;               // S / PV col group
    const int jtQ = (rW >> 3) + 5 * hh;       // QE band tile base (5 tiles)
    const int jtK = (6 - (rW >> 3)) + 5 * hh; // KE band tile base (5 tiles)
    const int pg  = ((gid & 3) << 1) | (gid >> 2);  // perm low bits of gid

    const int srow = t >> 2;              // softmax row
    const int sq   = t & 3;               // softmax quarter

    // per-thread async-copy coords
    const int kvr = t >> 4, kvd = (t & 15) * 4;   // K/V: 4 rows' worth per pass

    // Load Q tile (already permuted tf32 bits), plain loads (once).
#pragma unroll
    for (int p = 0; p < 4; p++) {
        int f = t + p * 256;
        int l = f >> 4, dg = (f & 15) * 4;
        *(float4*)(&sm.Qs[l * QS + dg]) = *(const float4*)(qp + (size_t)(l0 + l) * HD + dg);
    }

    // Prefetch iter 0 into buffer 0.
    {
        const int r0 = 0;
        const int jbase = l0 - r0 + 960;
#pragma unroll
        for (int p = 0; p < 4; p++) {
            int f = t + p * 256;
            int r = f >> 4, dg = (f & 15) * 4;
            cp16((uint32_t)__cvta_generic_to_shared(&sm.Ks[0][r * QS + dg]),
                 kp + (size_t)(r0 + r) * HD + dg);
            cp16((uint32_t)__cvta_generic_to_shared(&sm.Vs[0][r * QS + dg]),
                 vp + (size_t)(r0 + r) * HD + dg);
        }
#pragma unroll
        for (int p = 0; p < 8; p++) {
            int f = t + p * 256;
            int j = f >> 4, dg = (f & 15) * 4;
            if (j < 127)
                cp16((uint32_t)__cvta_generic_to_shared(&sm.Es[0][j * QS + dg]),
                     g_e + (size_t)(jbase + j) * HD + dg);
        }
        cp_commit();
    }

    float o_acc[4][4];
#pragma unroll
    for (int nt = 0; nt < 4; nt++)
#pragma unroll
        for (int e = 0; e < 4; e++) o_acc[nt][e] = 0.f;

    float m_run = -1e30f, s_run = 0.f;

    for (int it = 0; it < 16; it++) {
        const int buf = it & 1;
        // ---- prefetch next tile into other buffer (overlaps compute) ----
        if (it + 1 < 16) {
            const int nbuf = buf ^ 1;
            const int r0n = (it + 1) * 64;
            const int jbn = l0 - r0n + 960;
#pragma unroll
            for (int p = 0; p < 4; p++) {
                int f = t + p * 256;
                int r = f >> 4, dg = (f & 15) * 4;
                cp16((uint32_t)__cvta_generic_to_shared(&sm.Ks[nbuf][r * QS + dg]),
                     kp + (size_t)(r0n + r) * HD + dg);
                cp16((uint32_t)__cvta_generic_to_shared(&sm.Vs[nbuf][r * QS + dg]),
                     vp + (size_t)(r0n + r) * HD + dg);
            }
#pragma unroll
            for (int p = 0; p < 8; p++) {
                int f = t + p * 256;
                int j = f >> 4, dg = (f & 15) * 4;
                if (j < 127)
                    cp16((uint32_t)__cvta_generic_to_shared(&sm.Es[nbuf][j * QS + dg]),
                         g_e + (size_t)(jbn + j) * HD + dg);
            }
        }
        cp_commit();
        cp_wait<1>();          // current iter's data landed (this thread)
        __syncthreads();       // ... and everyone else's

        const float* Ks = sm.Ks[buf];
        const float* Vs = sm.Vs[buf];
        const float* Es = sm.Es[buf];

        // ---- S = Q K^T  and  QE = Q E^T (banded), shared A fragments ----
        float sacc[4][4], qacc[5][4];
#pragma unroll
        for (int nt = 0; nt < 4; nt++)
#pragma unroll
            for (int e = 0; e < 4; e++) sacc[nt][e] = 0.f;
#pragma unroll
        for (int tt = 0; tt < 5; tt++)
#pragma unroll
            for (int e = 0; e < 4; e++) qacc[tt][e] = 0.f;

#pragma unroll
        for (int ks = 0; ks < 8; ks++) {
            const int ka = ks * 8 + 2 * t4;
            float2 aL = *(const float2*)(&sm.Qs[(rW + gid) * QS + ka]);
            float2 aH = *(const float2*)(&sm.Qs[(rW + gid + 8) * QS + ka]);
            uint32_t a0 = fbits(aL.x), a1 = fbits(aH.x);
            uint32_t a2 = fbits(aL.y), a3 = fbits(aH.y);
#pragma unroll
            for (int nt = 0; nt < 4; nt++) {
                float2 bb = *(const float2*)(&Ks[(cS + nt * 8 + gid) * QS + ka]);
                mma_tf32(sacc[nt], a0, a1, a2, a3, fbits(bb.x), fbits(bb.y));
            }
#pragma unroll
            for (int tt = 0; tt < 5; tt++) {
                float2 bb = *(const float2*)(&Es[((jtQ + tt) * 8 + gid) * QS + ka]);
                mma_tf32(qacc[tt], a0, a1, a2, a3, fbits(bb.x), fbits(bb.y));
            }
        }
        // store S (scalar, permuted columns)
#pragma unroll
        for (int nt = 0; nt < 4; nt++) {
            int c = cS + nt * 8 + 2 * t4;
            int p0 = perm8(c);
            sm.S[(rW + gid) * QS + p0]         = sacc[nt][0];
            sm.S[(rW + gid) * QS + p0 + 2]     = sacc[nt][1];
            sm.S[(rW + gid + 8) * QS + p0]     = sacc[nt][2];
            sm.S[(rW + gid + 8) * QS + p0 + 2] = sacc[nt][3];
        }
        __syncthreads();

        // ---- scatter QE: (l, j) -> S[l][perm(r)], r = l - j + 63 ----
#pragma unroll
        for (int tt = 0; tt < 5; tt++) {
            int jc = (jtQ + tt) * 8 + 2 * t4;
#pragma unroll
            for (int e = 0; e < 4; e++) {
                int l = rW + gid + ((e >> 1) << 3);
                int j = jc + (e & 1);
                int r = l - j + 63;
                if ((unsigned)r < 64u) atomicAdd(&sm.S[l * QS + perm8(r)], qacc[tt][e]);
            }
        }

        // ---- KE = K E^T (banded) ----
        float kacc[5][4];
#pragma unroll
        for (int tt = 0; tt < 5; tt++)
#pragma unroll
            for (int e = 0; e < 4; e++) kacc[tt][e] = 0.f;
#pragma unroll
        for (int ks = 0; ks < 8; ks++) {
            const int ka = ks * 8 + 2 * t4;
            float2 aL = *(const float2*)(&Ks[(rW + gid) * QS + ka]);
            float2 aH = *(const float2*)(&Ks[(rW + gid + 8) * QS + ka]);
            uint32_t a0 = fbits(aL.x), a1 = fbits(aH.x);
            uint32_t a2 = fbits(aL.y), a3 = fbits(aH.y);
#pragma unroll
            for (int tt = 0; tt < 5; tt++) {
                float2 bb = *(const float2*)(&Es[((jtK + tt) * 8 + gid) * QS + ka]);
                mma_tf32(kacc[tt], a0, a1, a2, a3, fbits(bb.x), fbits(bb.y));
            }
        }
        // scatter KE: (r, j) -> S[l][perm(r)], l = r + j - 63
#pragma unroll
        for (int tt = 0; tt < 5; tt++) {
            int jc = (jtK + tt) * 8 + 2 * t4;
#pragma unroll
            for (int e = 0; e < 4; e++) {
                int rb = (e >> 1) << 3;
                int r = rW + gid + rb;
                int j = jc + (e & 1);
                int l = r + j - 63;
                if ((unsigned)l < 64u)
                    atomicAdd(&sm.S[l * QS + rW + rb + pg], kacc[tt][e]);
            }
        }
        __syncthreads();

        // ---- online softmax: 4 threads/row, 16 contiguous slots each ----
        {
            float4 sv[4];
            float pm = -1e30f;
#pragma unroll
            for (int i = 0; i < 4; i++) {
                sv[i] = *(const float4*)(&sm.S[srow * QS + sq * 16 + 4 * i]);
                sv[i].x *= SCALE; sv[i].y *= SCALE; sv[i].z *= SCALE; sv[i].w *= SCALE;
                pm = fmaxf(pm, fmaxf(fmaxf(sv[i].x, sv[i].y), fmaxf(sv[i].z, sv[i].w)));
            }
            pm = fmaxf(pm, __shfl_xor_sync(0xffffffffu, pm, 1));
            pm = fmaxf(pm, __shfl_xor_sync(0xffffffffu, pm, 2));
            float mn = fmaxf(m_run, pm);
            float fac = __expf(m_run - mn);
            m_run = mn;
            float ps = 0.f;
#pragma unroll
            for (int i = 0; i < 4; i++) {
                float4 pv;
                pv.x = __expf(sv[i].x - mn); pv.y = __expf(sv[i].y - mn);
                pv.z = __expf(sv[i].z - mn); pv.w = __expf(sv[i].w - mn);
                ps += (pv.x + pv.y) + (pv.z + pv.w);
                float4 pb;
                pb.x = __uint_as_float(f2tf(pv.x)); pb.y = __uint_as_float(f2tf(pv.y));
                pb.z = __uint_as_float(f2tf(pv.z)); pb.w = __uint_as_float(f2tf(pv.w));
                *(float4*)(&sm.S[srow * QS + sq * 16 + 4 * i]) = pb;
            }
            ps += __shfl_xor_sync(0xffffffffu, ps, 1);
            ps += __shfl_xor_sync(0xffffffffu, ps, 2);
            s_run = s_run * fac + ps;
            if (sq == 0) sm.fac_s[srow] = fac;
        }
        __syncthreads();

        // ---- rescale O, then O += P V ----
        {
            float f0 = sm.fac_s[rW + gid];
            float f1 = sm.fac_s[rW + gid + 8];
#pragma unroll
            for (int nt = 0; nt < 4; nt++) {
                o_acc[nt][0] *= f0; o_acc[nt][1] *= f0;
                o_acc[nt][2] *= f1; o_acc[nt][3] *= f1;
            }
#pragma unroll
            for (int ks = 0; ks < 8; ks++) {
                const int ka = ks * 8 + 2 * t4;
                float2 aL = *(const float2*)(&sm.S[(rW + gid) * QS + ka]);
                float2 aH = *(const float2*)(&sm.S[(rW + gid + 8) * QS + ka]);
                uint32_t a0 = fbits(aL.x), a1 = fbits(aH.x);
                uint32_t a2 = fbits(aL.y), a3 = fbits(aH.y);
#pragma unroll
                for (int nt = 0; nt < 4; nt++) {
                    int n0 = cS + nt * 8 + gid;
                    uint32_t b0 = fbits(Vs[(ks * 8 + t4) * QS + n0]);
                    uint32_t b1 = fbits(Vs[(ks * 8 + t4 + 4) * QS + n0]);
                    mma_tf32(o_acc[nt], a0, a1, a2, a3, b0, b1);
                }
            }
        }
        __syncthreads();
    }

    if (sq == 0) sm.inv_s[srow] = 1.f / s_run;
    __syncthreads();

    // ---- epilogue ----
    {
        float i0 = sm.inv_s[rW + gid];
        float i1 = sm.inv_s[rW + gid + 8];
        int lg0 = l0 + rW + gid;
        int lg1 = lg0 + 8;
#pragma unroll
        for (int nt = 0; nt < 4; nt++) {
            int c = cS + nt * 8 + 2 * t4;
            float2 v0 = make_float2(o_acc[nt][0] * i0, o_acc[nt][1] * i0);
            float2 v1 = make_float2(o_acc[nt][2] * i1, o_acc[nt][3] * i1);
            *(float2*)(out + ((size_t)b * LL + lg0) * DD + h * HD + c) = v0;
            *(float2*)(out + ((size_t)b * LL + lg1) * DD + h * HD + c) = v1;
        }
    }
}

// ---------------------------------------------------------------------------
extern "C" void kernel_launch(void* const* d_in, const int* in_sizes, int n_in,
                              void* d_out, int out_size) {
    const float* x        = (const float*)d_in[0];
    const float* Wqkv     = (const float*)d_in[1];
    const float* bqkv     = (const float*)d_in[2];
    const float* dist_emb = (const float*)d_in[3];
    float* out = (float*)d_out;

    (void)in_sizes; (void)n_in; (void)out_size;

    cudaFuncSetAttribute(attn_kernel, cudaFuncAttributeMaxDynamicSharedMemorySize,
                         (int)sizeof(AttnSmem));

    prep_e_kernel<<<512, 256>>>(dist_emb);
    qkv_kernel<<<dim3(24, 32), 256>>>(x, Wqkv, bqkv);
    attn_kernel<<<dim3(16, 64), 256, sizeof(AttnSmem)>>>(out);
}

// round 9
// speedup vs baseline: 3.8898x; 1.1348x over previous
#include <cuda_runtime.h>
#include <cstdint>

#define BB 4
#define LL 1024
#define DD 1024
#define HH 16
#define HD 64
#define BH (BB*HH)
#define SCALE 0.125f

// q/k stored tf32-bit + k-pair-permuted within 8; v natural tf32-bit. [BH][L][HD]
__device__ float g_q[BH * LL * HD];
__device__ float g_k[BH * LL * HD];
__device__ float g_v[BH * LL * HD];
// dist_emb, tf32-cvt'd + permuted rows: [2047][64]
__device__ float g_e[2047 * HD];

__device__ __forceinline__ uint32_t f2tf(float f) {
    uint32_t u;
    asm("cvt.rna.tf32.f32 %0, %1;" : "=r"(u) : "f"(f));
    return u;
}
__device__ __forceinline__ uint32_t fbits(float f) { return __float_as_uint(f); }
__device__ __forceinline__ int perm8(int k) {
    return (k & ~7) | (((k & 3) << 1) | ((k >> 2) & 1));
}
__device__ __forceinline__ void cp16(uint32_t dst, const void* src) {
    asm volatile("cp.async.ca.shared.global [%0], [%1], 16;" :: "r"(dst), "l"(src));
}
__device__ __forceinline__ void cp_commit() {
    asm volatile("cp.async.commit_group;");
}
template <int N>
__device__ __forceinline__ void cp_wait() {
    asm volatile("cp.async.wait_group %0;" :: "n"(N));
}

__device__ __forceinline__ void mma_tf32(float c[4], uint32_t a0, uint32_t a1,
                                         uint32_t a2, uint32_t a3,
                                         uint32_t b0, uint32_t b1) {
    asm volatile(
        "mma.sync.aligned.m16n8k8.row.col.f32.tf32.tf32.f32 "
        "{%0,%1,%2,%3},{%4,%5,%6,%7},{%8,%9},{%0,%1,%2,%3};"
        : "+f"(c[0]), "+f"(c[1]), "+f"(c[2]), "+f"(c[3])
        : "r"(a0), "r"(a1), "r"(a2), "r"(a3), "r"(b0), "r"(b1));
}

// ---------------------------------------------------------------------------
// Kernel 0: convert dist_emb -> tf32 bits, k-pair permuted rows.
// ---------------------------------------------------------------------------
__global__ __launch_bounds__(256) void prep_e_kernel(const float* __restrict__ dist_emb) {
    int idx = blockIdx.x * 256 + threadIdx.x;
    if (idx < 2047 * HD) {
        int j = idx >> 6, d = idx & 63;
        g_e[j * HD + perm8(d)] = __uint_as_float(f2tf(dist_emb[idx]));
    }
}

// ---------------------------------------------------------------------------
// Kernel 1: QKV projection with tf32 mma. C[4096,3072] = x @ W + b.
// ---------------------------------------------------------------------------
#define AS_STRIDE 20
#define BS_STRIDE 136

__global__ __launch_bounds__(256) void qkv_kernel(const float* __restrict__ x,
                                                  const float* __restrict__ w,
                                                  const float* __restrict__ bias) {
    __shared__ float As[128 * AS_STRIDE];   // [m][k] tf32 bits
    __shared__ float Bs[16 * BS_STRIDE];    // [k][n] tf32 bits

    const int t    = threadIdx.x;
    const int lane = t & 31;
    const int wrp  = t >> 5;
    const int gid  = lane >> 2;
    const int t4   = lane & 3;
    const int m0 = blockIdx.y * 128;
    const int n0 = blockIdx.x * 128;
    const int mwb = (wrp & 3) * 32;
    const int nwb = (wrp >> 2) * 64;

    float cacc[2][8][4];
#pragma unroll
    for (int mt = 0; mt < 2; mt++)
#pragma unroll
        for (int nt = 0; nt < 8; nt++)
#pragma unroll
            for (int e = 0; e < 4; e++) cacc[mt][nt][e] = 0.f;

    int xrow[2], xk[2], wrow[2], wn[2];
#pragma unroll
    for (int p = 0; p < 2; p++) {
        int f = t + p * 256;
        xrow[p] = f >> 2;  xk[p] = (f & 3) * 4;       // 128 rows x 16 k
        wrow[p] = f >> 5;  wn[p] = (f & 31) * 4;      // 16 k x 128 n
    }

    float4 xa[2], wb[2];
#pragma unroll
    for (int p = 0; p < 2; p++) {
        xa[p] = *(const float4*)(x + (size_t)(m0 + xrow[p]) * 1024 + 0 + xk[p]);
        wb[p] = *(const float4*)(w + (size_t)(0 + wrow[p]) * 3072 + n0 + wn[p]);
    }

    for (int k0 = 0; k0 < 1024; k0 += 16) {
        __syncthreads();
#pragma unroll
        for (int p = 0; p < 2; p++) {
            float* a = &As[xrow[p] * AS_STRIDE + xk[p]];
            a[0] = __uint_as_float(f2tf(xa[p].x));
            a[1] = __uint_as_float(f2tf(xa[p].y));
            a[2] = __uint_as_float(f2tf(xa[p].z));
            a[3] = __uint_as_float(f2tf(xa[p].w));
            float* bq = &Bs[wrow[p] * BS_STRIDE + wn[p]];
            bq[0] = __uint_as_float(f2tf(wb[p].x));
            bq[1] = __uint_as_float(f2tf(wb[p].y));
            bq[2] = __uint_as_float(f2tf(wb[p].z));
            bq[3] = __uint_as_float(f2tf(wb[p].w));
        }
        __syncthreads();
        if (k0 + 16 < 1024) {
#pragma unroll
            for (int p = 0; p < 2; p++) {
                xa[p] = *(const float4*)(x + (size_t)(m0 + xrow[p]) * 1024 + (k0 + 16) + xk[p]);
                wb[p] = *(const float4*)(w + (size_t)((k0 + 16) + wrow[p]) * 3072 + n0 + wn[p]);
            }
        }
#pragma unroll
        for (int ks = 0; ks < 2; ks++) {
            const int kb = ks * 8;
            uint32_t a[2][4];
#pragma unroll
            for (int mt = 0; mt < 2; mt++) {
                int base = mwb + mt * 16;
                a[mt][0] = fbits(As[(base + gid) * AS_STRIDE + kb + t4]);
                a[mt][1] = fbits(As[(base + gid + 8) * AS_STRIDE + kb + t4]);
                a[mt][2] = fbits(As[(base + gid) * AS_STRIDE + kb + t4 + 4]);
                a[mt][3] = fbits(As[(base + gid + 8) * AS_STRIDE + kb + t4 + 4]);
            }
#pragma unroll
            for (int nt = 0; nt < 8; nt++) {
                uint32_t b0 = fbits(Bs[(kb + t4) * BS_STRIDE + nwb + nt * 8 + gid]);
                uint32_t b1 = fbits(Bs[(kb + t4 + 4) * BS_STRIDE + nwb + nt * 8 + gid]);
                mma_tf32(cacc[0][nt], a[0][0], a[0][1], a[0][2], a[0][3], b0, b1);
                mma_tf32(cacc[1][nt], a[1][0], a[1][1], a[1][2], a[1][3], b0, b1);
            }
        }
    }

    // Epilogue: +bias, cvt tf32; q/k stored PERMUTED within 8-col blocks, v natural.
#pragma unroll
    for (int nt = 0; nt < 8; nt++) {
        int n = n0 + nwb + nt * 8 + 2 * t4;      // even
        float b0 = bias[n], b1 = bias[n + 1];
        int which = n >> 10;
        int rem = n & 1023;
        int h = rem >> 6, hd = rem & 63;
        float* dst = (which == 0) ? g_q : ((which == 1) ? g_k : g_v);
        int p0 = perm8(hd);                      // hd even -> pair at p0, p0+2
#pragma unroll
        for (int mt = 0; mt < 2; mt++) {
#pragma unroll
            for (int hf = 0; hf < 2; hf++) {
                int m = m0 + mwb + mt * 16 + gid + hf * 8;
                int bb = m >> 10, l = m & 1023;
                float v0 = __uint_as_float(f2tf(cacc[mt][nt][hf * 2 + 0] + b0));
                float v1 = __uint_as_float(f2tf(cacc[mt][nt][hf * 2 + 1] + b1));
                float* row = dst + (((size_t)bb * HH + h) * LL + l) * HD;
                if (which == 2) {
                    *(float2*)(row + hd) = make_float2(v0, v1);
                } else {
                    row[p0]     = v0;
                    row[p0 + 2] = v1;
                }
            }
        }
    }
}

// ---------------------------------------------------------------------------
// Kernel 2: fused attention. Single-buffered smem (108.5KB) so TWO CTAs
// co-reside per SM; phase-aware cp.async prefetch (K/E after KE phase,
// V after PV phase) keeps most of the pipelining within single buffers.
// ---------------------------------------------------------------------------
#define QS 72   // unified row stride (8 mod 32 -> conflict-free paired loads)

struct AttnSmem {
    float Qs[64 * QS];    // [l][perm(d)]
    float Ks[64 * QS];    // [r][perm(d)]
    float Vs[64 * QS];    // [r][d] natural
    float Es[128 * QS];   // [j][perm(d)] (row 127 never written/used)
    float S[64 * QS];     // [l][perm(r)] scores -> P
    float fac_s[64];
    float inv_s[64];
};

__global__ __launch_bounds__(256, 2) void attn_kernel(float* __restrict__ out) {
    extern __shared__ char smem_raw[];
    AttnSmem& sm = *(AttnSmem*)smem_raw;

    const int t    = threadIdx.x;
    const int lane = t & 31;
    const int wrp  = t >> 5;
    const int gid  = lane >> 2;
    const int t4   = lane & 3;

    const int bh = blockIdx.y;
    const int l0 = blockIdx.x * 64;
    const int b  = bh >> 4;
    const int h  = bh & 15;

    const float* qp = g_q + (size_t)bh * LL * HD;
    const float* kp = g_k + (size_t)bh * LL * HD;
    const float* vp = g_v + (size_t)bh * LL * HD;

    const int rW = (wrp & 3) * 16;        // row group base
    const int hh = wrp >> 2;              // column half
    const int cS = hh * 32;               // S / PV col group
    const int jtQ = (rW >> 3) + 5 * hh;       // QE band tile base (5 tiles)
    const int jtK = (6 - (rW >> 3)) + 5 * hh; // KE band tile base (5 tiles)
    const int pg  = ((gid & 3) << 1) | (gid >> 2);  // perm low bits of gid

    const int srow = t >> 2;              // softmax row
    const int sq   = t & 3;               // softmax quarter

    // Load Q tile (already permuted tf32 bits), plain loads (once).
#pragma unroll
    for (int p = 0; p < 4; p++) {
        int f = t + p * 256;
        int l = f >> 4, dg = (f & 15) * 4;
        *(float4*)(&sm.Qs[l * QS + dg]) = *(const float4*)(qp + (size_t)(l0 + l) * HD + dg);
    }

    // Prefetch iter 0: K/E as group 1, V as group 2.
    {
        const int jbase = l0 + 960;
#pragma unroll
        for (int p = 0; p < 4; p++) {
            int f = t + p * 256;
            int r = f >> 4, dg = (f & 15) * 4;
            cp16((uint32_t)__cvta_generic_to_shared(&sm.Ks[r * QS + dg]),
                 kp + (size_t)r * HD + dg);
        }
#pragma unroll
        for (int p = 0; p < 8; p++) {
            int f = t + p * 256;
            int j = f >> 4, dg = (f & 15) * 4;
            if (j < 127)
                cp16((uint32_t)__cvta_generic_to_shared(&sm.Es[j * QS + dg]),
                     g_e + (size_t)(jbase + j) * HD + dg);
        }
        cp_commit();
#pragma unroll
        for (int p = 0; p < 4; p++) {
            int f = t + p * 256;
            int r = f >> 4, dg = (f & 15) * 4;
            cp16((uint32_t)__cvta_generic_to_shared(&sm.Vs[r * QS + dg]),
                 vp + (size_t)r * HD + dg);
        }
        cp_commit();
    }

    float o_acc[4][4];
#pragma unroll
    for (int nt = 0; nt < 4; nt++)
#pragma unroll
        for (int e = 0; e < 4; e++) o_acc[nt][e] = 0.f;

    float m_run = -1e30f, s_run = 0.f;

    for (int it = 0; it < 16; it++) {
        cp_wait<1>();          // K/E of this iter landed (V group may pend)
        __syncthreads();

        // ---- S = Q K^T  and  QE = Q E^T (banded), shared A fragments ----
        float sacc[4][4], qacc[5][4];
#pragma unroll
        for (int nt = 0; nt < 4; nt++)
#pragma unroll
            for (int e = 0; e < 4; e++) sacc[nt][e] = 0.f;
#pragma unroll
        for (int tt = 0; tt < 5; tt++)
#pragma unroll
            for (int e = 0; e < 4; e++) qacc[tt][e] = 0.f;

#pragma unroll
        for (int ks = 0; ks < 8; ks++) {
            const int ka = ks * 8 + 2 * t4;
            float2 aL = *(const float2*)(&sm.Qs[(rW + gid) * QS + ka]);
            float2 aH = *(const float2*)(&sm.Qs[(rW + gid + 8) * QS + ka]);
            uint32_t a0 = fbits(aL.x), a1 = fbits(aH.x);
            uint32_t a2 = fbits(aL.y), a3 = fbits(aH.y);
#pragma unroll
            for (int nt = 0; nt < 4; nt++) {
                float2 bb = *(const float2*)(&sm.Ks[(cS + nt * 8 + gid) * QS + ka]);
                mma_tf32(sacc[nt], a0, a1, a2, a3, fbits(bb.x), fbits(bb.y));
            }
#pragma unroll
            for (int tt = 0; tt < 5; tt++) {
                float2 bb = *(const float2*)(&sm.Es[((jtQ + tt) * 8 + gid) * QS + ka]);
                mma_tf32(qacc[tt], a0, a1, a2, a3, fbits(bb.x), fbits(bb.y));
            }
        }
        // store S (scalar, permuted columns)
#pragma unroll
        for (int nt = 0; nt < 4; nt++) {
            int c = cS + nt * 8 + 2 * t4;
            int p0 = perm8(c);
            sm.S[(rW + gid) * QS + p0]         = sacc[nt][0];
            sm.S[(rW + gid) * QS + p0 + 2]     = sacc[nt][1];
            sm.S[(rW + gid + 8) * QS + p0]     = sacc[nt][2];
            sm.S[(rW + gid + 8) * QS + p0 + 2] = sacc[nt][3];
        }
        __syncthreads();

        // ---- scatter QE: (l, j) -> S[l][perm(r)], r = l - j + 63 ----
#pragma unroll
        for (int tt = 0; tt < 5; tt++) {
            int jc = (jtQ + tt) * 8 + 2 * t4;
#pragma unroll
            for (int e = 0; e < 4; e++) {
                int l = rW + gid + ((e >> 1) << 3);
                int j = jc + (e & 1);
                int r = l - j + 63;
                if ((unsigned)r < 64u) atomicAdd(&sm.S[l * QS + perm8(r)], qacc[tt][e]);
            }
        }

        // ---- KE = K E^T (banded) ----
        float kacc[5][4];
#pragma unroll
        for (int tt = 0; tt < 5; tt++)
#pragma unroll
            for (int e = 0; e < 4; e++) kacc[tt][e] = 0.f;
#pragma unroll
        for (int ks = 0; ks < 8; ks++) {
            const int ka = ks * 8 + 2 * t4;
            float2 aL = *(const float2*)(&sm.Ks[(rW + gid) * QS + ka]);
            float2 aH = *(const float2*)(&sm.Ks[(rW + gid + 8) * QS + ka]);
            uint32_t a0 = fbits(aL.x), a1 = fbits(aH.x);
            uint32_t a2 = fbits(aL.y), a3 = fbits(aH.y);
#pragma unroll
            for (int tt = 0; tt < 5; tt++) {
                float2 bb = *(const float2*)(&sm.Es[((jtK + tt) * 8 + gid) * QS + ka]);
                mma_tf32(kacc[tt], a0, a1, a2, a3, fbits(bb.x), fbits(bb.y));
            }
        }
        // scatter KE: (r, j) -> S[l][perm(r)], l = r + j - 63
#pragma unroll
        for (int tt = 0; tt < 5; tt++) {
            int jc = (jtK + tt) * 8 + 2 * t4;
#pragma unroll
            for (int e = 0; e < 4; e++) {
                int rb = (e >> 1) << 3;
                int r = rW + gid + rb;
                int j = jc + (e & 1);
                int l = r + j - 63;
                if ((unsigned)l < 64u)
                    atomicAdd(&sm.S[l * QS + rW + rb + pg], kacc[tt][e]);
            }
        }
        __syncthreads();   // all bias adds done; K/E buffers now free

        // ---- prefetch K/E for next iter (overlaps softmax + PV) ----
        if (it + 1 < 16) {
            const int r0n = (it + 1) * 64;
            const int jbn = l0 - r0n + 960;
#pragma unroll
            for (int p = 0; p < 4; p++) {
                int f = t + p * 256;
                int r = f >> 4, dg = (f & 15) * 4;
                cp16((uint32_t)__cvta_generic_to_shared(&sm.Ks[r * QS + dg]),
                     kp + (size_t)(r0n + r) * HD + dg);
            }
#pragma unroll
            for (int p = 0; p < 8; p++) {
                int f = t + p * 256;
                int j = f >> 4, dg = (f & 15) * 4;
                if (j < 127)
                    cp16((uint32_t)__cvta_generic_to_shared(&sm.Es[j * QS + dg]),
                         g_e + (size_t)(jbn + j) * HD + dg);
            }
        }
        cp_commit();

        // ---- online softmax: 4 threads/row, 16 contiguous slots each ----
        {
            float4 sv[4];
            float pm = -1e30f;
#pragma unroll
            for (int i = 0; i < 4; i++) {
                sv[i] = *(const float4*)(&sm.S[srow * QS + sq * 16 + 4 * i]);
                sv[i].x *= SCALE; sv[i].y *= SCALE; sv[i].z *= SCALE; sv[i].w *= SCALE;
                pm = fmaxf(pm, fmaxf(fmaxf(sv[i].x, sv[i].y), fmaxf(sv[i].z, sv[i].w)));
            }
            pm = fmaxf(pm, __shfl_xor_sync(0xffffffffu, pm, 1));
            pm = fmaxf(pm, __shfl_xor_sync(0xffffffffu, pm, 2));
            float mn = fmaxf(m_run, pm);
            float fac = __expf(m_run - mn);
            m_run = mn;
            float ps = 0.f;
#pragma unroll
            for (int i = 0; i < 4; i++) {
                float4 pv;
                pv.x = __expf(sv[i].x - mn); pv.y = __expf(sv[i].y - mn);
                pv.z = __expf(sv[i].z - mn); pv.w = __expf(sv[i].w - mn);
                ps += (pv.x + pv.y) + (pv.z + pv.w);
                float4 pb;
                pb.x = __uint_as_float(f2tf(pv.x)); pb.y = __uint_as_float(f2tf(pv.y));
                pb.z = __uint_as_float(f2tf(pv.z)); pb.w = __uint_as_float(f2tf(pv.w));
                *(float4*)(&sm.S[srow * QS + sq * 16 + 4 * i]) = pb;
            }
            ps += __shfl_xor_sync(0xffffffffu, ps, 1);
            ps += __shfl_xor_sync(0xffffffffu, ps, 2);
            s_run = s_run * fac + ps;
            if (sq == 0) sm.fac_s[srow] = fac;
        }
        cp_wait<1>();          // V of this iter landed (K/E next-iter may pend)
        __syncthreads();       // P + fac ready, V ready

        // ---- rescale O, then O += P V ----
        {
            float f0 = sm.fac_s[rW + gid];
            float f1 = sm.fac_s[rW + gid + 8];
#pragma unroll
            for (int nt = 0; nt < 4; nt++) {
                o_acc[nt][0] *= f0; o_acc[nt][1] *= f0;
                o_acc[nt][2] *= f1; o_acc[nt][3] *= f1;
            }
#pragma unroll
            for (int ks = 0; ks < 8; ks++) {
                const int ka = ks * 8 + 2 * t4;
                float2 aL = *(const float2*)(&sm.S[(rW + gid) * QS + ka]);
                float2 aH = *(const float2*)(&sm.S[(rW + gid + 8) * QS + ka]);
                uint32_t a0 = fbits(aL.x), a1 = fbits(aH.x);
                uint32_t a2 = fbits(aL.y), a3 = fbits(aH.y);
#pragma unroll
                for (int nt = 0; nt < 4; nt++) {
                    int n0 = cS + nt * 8 + gid;
                    uint32_t b0 = fbits(sm.Vs[(ks * 8 + t4) * QS + n0]);
                    uint32_t b1 = fbits(sm.Vs[(ks * 8 + t4 + 4) * QS + n0]);
                    mma_tf32(o_acc[nt], a0, a1, a2, a3, b0, b1);
                }
            }
        }
        __syncthreads();       // V buffer free

        // ---- prefetch V for next iter ----
        if (it + 1 < 16) {
            const int r0n = (it + 1) * 64;
#pragma unroll
            for (int p = 0; p < 4; p++) {
                int f = t + p * 256;
                int r = f >> 4, dg = (f & 15) * 4;
                cp16((uint32_t)__cvta_generic_to_shared(&sm.Vs[r * QS + dg]),
                     vp + (size_t)(r0n + r) * HD + dg);
            }
        }
        cp_commit();
    }

    if (sq == 0) sm.inv_s[srow] = 1.f / s_run;
    __syncthreads();

    // ---- epilogue ----
    {
        float i0 = sm.inv_s[rW + gid];
        float i1 = sm.inv_s[rW + gid + 8];
        int lg0 = l0 + rW + gid;
        int lg1 = lg0 + 8;
#pragma unroll
        for (int nt = 0; nt < 4; nt++) {
            int c = cS + nt * 8 + 2 * t4;
            float2 v0 = make_float2(o_acc[nt][0] * i0, o_acc[nt][1] * i0);
            float2 v1 = make_float2(o_acc[nt][2] * i1, o_acc[nt][3] * i1);
            *(float2*)(out + ((size_t)b * LL + lg0) * DD + h * HD + c) = v0;
            *(float2*)(out + ((size_t)b * LL + lg1) * DD + h * HD + c) = v1;
        }
    }
}

// ---------------------------------------------------------------------------
extern "C" void kernel_launch(void* const* d_in, const int* in_sizes, int n_in,
                              void* d_out, int out_size) {
    const float* x        = (const float*)d_in[0];
    const float* Wqkv     = (const float*)d_in[1];
    const float* bqkv     = (const float*)d_in[2];
    const float* dist_emb = (const float*)d_in[3];
    float* out = (float*)d_out;

    (void)in_sizes; (void)n_in; (void)out_size;

    cudaFuncSetAttribute(attn_kernel, cudaFuncAttributeMaxDynamicSharedMemorySize,
                         (int)sizeof(AttnSmem));

    prep_e_kernel<<<512, 256>>>(dist_emb);
    qkv_kernel<<<dim3(24, 32), 256>>>(x, Wqkv, bqkv);
    attn_kernel<<<dim3(16, 64), 256, sizeof(AttnSmem)>>>(out);
}